// round 16
// baseline (speedup 1.0000x reference)
#include <cuda_runtime.h>
#include <cuda_bf16.h>
#include <cstdint>

#define NB    8192
#define NFEAT 128
#define NUSER 1000
#define NU_PAD 1024
#define NCATE 1400
#define NP    95
#define KV    224     // virtual K: 128 pitm + 95 cbiasb + 1 pad

// Scratch (device globals; zero-initialized at module load)
__device__ __align__(256) __nv_bfloat16 g_ah[NB * KV];        // A hi, row-major [b][k]
__device__ __align__(256) __nv_bfloat16 g_al[NB * KV];        // A lo
__device__ __align__(256) __nv_bfloat16 g_uh[KV * NU_PAD];    // B hi, K-major [k][u]
__device__ __align__(256) __nv_bfloat16 g_ul[KV * NU_PAD];    // B lo
__device__ float g_p0[NB * 96];
__device__ float g_s[NB];
__device__ float g_uu[NUSER];
__device__ int   g_cnt[NCATE];   // zero at load; itmq resets after use
__device__ int   g_off[NCATE];
__device__ int   g_cur[NCATE];
__device__ int   g_rows[NB];

// ---------------------------------------------------------------------------
// PTX helpers
// ---------------------------------------------------------------------------
__device__ __forceinline__ void cpasync16(unsigned int dst_smem, const void* src) {
    asm volatile("cp.async.cg.shared.global [%0], [%1], 16;"
                 :: "r"(dst_smem), "l"(src));
}
__device__ __forceinline__ void cpasync_commit() {
    asm volatile("cp.async.commit_group;" ::: "memory");
}
__device__ __forceinline__ void cpasync_wait1() {
    asm volatile("cp.async.wait_group 1;" ::: "memory");
}
__device__ __forceinline__ void cpasync_wait0() {
    asm volatile("cp.async.wait_group 0;" ::: "memory");
}
__device__ __forceinline__ void ldsm_x4(unsigned* r, unsigned addr) {
    asm volatile("ldmatrix.sync.aligned.m8n8.x4.shared.b16 {%0,%1,%2,%3}, [%4];"
                 : "=r"(r[0]), "=r"(r[1]), "=r"(r[2]), "=r"(r[3]) : "r"(addr));
}
__device__ __forceinline__ void ldsm_x4_t(unsigned* r, unsigned addr) {
    asm volatile("ldmatrix.sync.aligned.m8n8.x4.trans.shared.b16 {%0,%1,%2,%3}, [%4];"
                 : "=r"(r[0]), "=r"(r[1]), "=r"(r[2]), "=r"(r[3]) : "r"(addr));
}
__device__ __forceinline__ void mma16816(float* c, const unsigned* a, const unsigned* b) {
    asm volatile(
        "mma.sync.aligned.m16n8k16.row.col.f32.bf16.bf16.f32 "
        "{%0,%1,%2,%3}, {%4,%5,%6,%7}, {%8,%9}, {%0,%1,%2,%3};"
        : "+f"(c[0]), "+f"(c[1]), "+f"(c[2]), "+f"(c[3])
        : "r"(a[0]), "r"(a[1]), "r"(a[2]), "r"(a[3]), "r"(b[0]), "r"(b[1]));
}
__device__ __forceinline__ void split_bf16(float x, __nv_bfloat16& h, __nv_bfloat16& l) {
    h = __float2bfloat16(x);
    l = __float2bfloat16(x - __bfloat162float(h));
}

// ---------------------------------------------------------------------------
// Fat kernel (slot 1): blocks 0..127 -> p0 GEMM (64 rows each, vectorized);
// blocks 128..159 -> histogram + cat chain (A cols 0..32).
// ---------------------------------------------------------------------------
__global__ __launch_bounds__(256, 2) void p0hist_kernel(
    const float* __restrict__ feat, const float* __restrict__ fc0_w,
    const float* __restrict__ fc0_b, const int* __restrict__ fcat,
    const float* __restrict__ cate_w, const float* __restrict__ cmat_w,
    const float* __restrict__ cbias_w)
{
    __shared__ __align__(16) float sw[128 * 100];
    __shared__ __align__(16) float sf[128 * 65];

    const int t = threadIdx.x;

    if (blockIdx.x < 128) {
        // ---------------- p0 part ----------------
        const int bm = blockIdx.x * 64;

        for (int L = t; L < NP * 128; L += 256) {
            int n = L >> 7, k = L & 127;
            sw[k * 100 + n] = fc0_w[L];
        }
        for (int L = t; L < 64 * 128; L += 256) {
            int m = L >> 7, k = L & 127;
            sf[k * 65 + m] = feat[(bm + m) * 128 + k];
        }
        __syncthreads();

        const int m  = t & 63;
        const int n0 = (t >> 6) * 24;   // 0,24,48,72 — 96B groups, 16B-aligned

        float acc[24];
        #pragma unroll
        for (int j = 0; j < 24; j++)
            acc[j] = (n0 + j < NP) ? fc0_b[n0 + j] : 0.f;

        #pragma unroll 4
        for (int k = 0; k < 128; k++) {
            float a = sf[k * 65 + m];
            const float4* wr4 = reinterpret_cast<const float4*>(&sw[k * 100 + n0]);
            #pragma unroll
            for (int q = 0; q < 6; q++) {
                float4 w = wr4[q];
                acc[q * 4 + 0] += a * w.x;
                acc[q * 4 + 1] += a * w.y;
                acc[q * 4 + 2] += a * w.z;
                acc[q * 4 + 3] += a * w.w;
            }
        }

        float* dst = &g_p0[(size_t)(bm + m) * 96 + n0];
        #pragma unroll
        for (int j = 0; j < 24; j++)
            if (n0 + j < 96) dst[j] = (n0 + j < NP) ? acc[j] : 0.f;
    } else {
        // ---------------- histcat part ----------------
        int b = (blockIdx.x - 128) * 256 + t;
        if (b >= NB) return;
        const int c0 = fcat[3 * b + 0];
        const int c1 = fcat[3 * b + 1];
        const int c2 = fcat[3 * b + 2];

        atomicAdd(&g_cnt[c2], 1);

        float cat1[11], cat2[11], cat3[11];
        #pragma unroll
        for (int j = 0; j < 11; j++) cat1[j] = cate_w[c0 * 11 + j];
        const float* m1 = cmat_w + c1 * 121;
        #pragma unroll
        for (int i = 0; i < 11; i++) {
            float a = cbias_w[c1 * 11 + i];
            #pragma unroll
            for (int j = 0; j < 11; j++) a += m1[i * 11 + j] * cat1[j];
            cat2[i] = a;
        }
        const float* m2 = cmat_w + c2 * 121;
        #pragma unroll
        for (int i = 0; i < 11; i++) {
            float a = cbias_w[c2 * 11 + i];
            #pragma unroll
            for (int j = 0; j < 11; j++) a += m2[i * 11 + j] * cat2[j];
            cat3[i] = a;
        }
        __nv_bfloat16* ah = &g_ah[(size_t)b * KV];
        __nv_bfloat16* al = &g_al[(size_t)b * KV];
        #pragma unroll
        for (int j = 0; j < 11; j++) {
            __nv_bfloat16 h, l;
            split_bf16(cat1[j], h, l); ah[j] = h;      al[j] = l;
            split_bf16(cat2[j], h, l); ah[11 + j] = h; al[11 + j] = l;
            split_bf16(cat3[j], h, l); ah[22 + j] = h; al[22 + j] = l;
        }
        ah[223] = __float2bfloat16(0.f);
        al[223] = __float2bfloat16(0.f);
    }
}

// ---------------------------------------------------------------------------
// scan (slot 2)
// ---------------------------------------------------------------------------
__global__ __launch_bounds__(256) void scan_kernel() {
    __shared__ int wsum[8];
    __shared__ int wexcl[8];
    const int t = threadIdx.x;
    const int lane = t & 31, warp = t >> 5;
    const int base = t * 6;
    int local[6];
    int s = 0;
    #pragma unroll
    for (int j = 0; j < 6; j++) {
        int idx = base + j;
        int v = (idx < NCATE) ? g_cnt[idx] : 0;
        local[j] = s;
        s += v;
    }
    int x = s;
    #pragma unroll
    for (int off = 1; off < 32; off <<= 1) {
        int y = __shfl_up_sync(0xffffffffu, x, off);
        if (lane >= off) x += y;
    }
    if (lane == 31) wsum[warp] = x;
    __syncthreads();
    if (warp == 0 && lane < 8) {
        int w = wsum[lane];
        int xx = w;
        #pragma unroll
        for (int off = 1; off < 8; off <<= 1) {
            int y = __shfl_up_sync(0xffu, xx, off);
            if (lane >= off) xx += y;
        }
        wexcl[lane] = xx - w;
    }
    __syncthreads();
    const int excl = (x - s) + wexcl[warp];
    #pragma unroll
    for (int j = 0; j < 6; j++) {
        int idx = base + j;
        if (idx < NCATE) {
            int o = excl + local[j];
            g_off[idx] = o;
            g_cur[idx] = o;
        }
    }
}

// ---------------------------------------------------------------------------
// scatter (slot 3)
// ---------------------------------------------------------------------------
__global__ void scatter_kernel(const int* __restrict__ fcat) {
    int b = blockIdx.x * 256 + threadIdx.x;
    if (b < NB) {
        int pos = atomicAdd(&g_cur[fcat[3 * b + 2]], 1);
        g_rows[pos] = b;
    }
}

// ---------------------------------------------------------------------------
// itmq (slot 4 -- gets profiled): per category; A cols 33..127 (itmq) and
// 128..222 (cbiasb split); s[b] = q.p0 + beta. Race-free count reset.
// ---------------------------------------------------------------------------
__global__ __launch_bounds__(256) void itmq_kernel(
    const float* __restrict__ cvismat_w, const float* __restrict__ cvisbias_w,
    const float* __restrict__ cbiasb_w)
{
    const int c = blockIdx.x;

    __shared__ int sn;
    if (threadIdx.x == 0) { sn = g_cnt[c]; g_cnt[c] = 0; }
    __syncthreads();
    const int n = sn;
    if (n == 0) return;

    __shared__ __align__(16) float sMT[96 * 97];   // [j][i] = M[i][j], stride 97
    __shared__ __align__(16) float sp[96][8];      // [j][row]  (float4-accessed)
    __shared__ __align__(16) float sq[96];
    __shared__ __align__(16) float svb[96];
    __shared__ __align__(16) float scb[96];
    __shared__ __nv_bfloat16 scbh[96];
    __shared__ __nv_bfloat16 scbl[96];
    __shared__ float sbeta;
    __shared__ int   srows[8];

    const int t = threadIdx.x;
    const int warp = t >> 5, lane = t & 31;

    // stage M transposed: warp w reads row i (coalesced), writes column-major
    {
        const float* Mrow = cvismat_w + (size_t)c * (NP * NP);
        for (int i = warp; i < NP; i += 8) {
            const float* src = Mrow + i * NP;
            float a0 = src[lane];
            float a1 = src[32 + lane];
            sMT[lane * 97 + i]        = a0;
            sMT[(32 + lane) * 97 + i] = a1;
            if (lane < 31) sMT[(64 + lane) * 97 + i] = src[64 + lane];
        }
    }
    if (t < NP) {
        float cbv = cbiasb_w[c * NP + t];
        scb[t] = cbv;
        svb[t] = cvisbias_w[c * NP + t];
        __nv_bfloat16 h, l;
        split_bf16(cbv, h, l);
        scbh[t] = h; scbl[t] = l;
    }
    if (t == NP) { scb[NP] = 0.f; svb[NP] = 0.f; }
    __syncthreads();

    // q[j] = sum_i cb[i] * M[i][j] ; conflict-free (bank = (j+i) mod 32)
    if (t < NP) {
        float qv = 0.f;
        const float* col = &sMT[t * 97];
        #pragma unroll 5
        for (int i = 0; i < NP; i++) qv += scb[i] * col[i];
        sq[t] = qv;
    }
    if (t == NP) sq[NP] = 0.f;
    if (warp == 0) {
        float v = scb[lane] * svb[lane] + scb[lane + 32] * svb[lane + 32]
                + scb[lane + 64] * svb[lane + 64];
        #pragma unroll
        for (int off = 16; off > 0; off >>= 1)
            v += __shfl_down_sync(0xffffffffu, v, off);
        if (lane == 0) sbeta = v;
    }

    const int start = g_off[c];
    const int h = t >> 7, tt = t & 127;

    for (int i0 = 0; i0 < n; i0 += 8) {
        __syncthreads();
        if (t < 8) srows[t] = (i0 + t < n) ? g_rows[start + i0 + t] : -1;
        __syncthreads();
        for (int L = t; L < 1024; L += 256) {
            int r = L >> 7, j = L & 127;
            if (j < 96) {
                int row = srows[r];
                sp[j][r] = (row >= 0) ? g_p0[(size_t)row * 96 + j] : 0.f;
            }
        }
        __syncthreads();

        if (tt < NP) {
            float a0 = svb[tt], a1 = a0, a2 = a0, a3 = a0;
            const float* mt = &sMT[tt];
            #pragma unroll 5
            for (int j = 0; j < NP; j++) {
                float m = mt[j * 97];
                float4 pv = *reinterpret_cast<const float4*>(&sp[j][h * 4]);
                a0 += m * pv.x; a1 += m * pv.y; a2 += m * pv.z; a3 += m * pv.w;
            }
            float av[4] = {a0, a1, a2, a3};
            __nv_bfloat16 ch = scbh[tt], clo = scbl[tt];
            #pragma unroll
            for (int r = 0; r < 4; r++) {
                int row = srows[h * 4 + r];
                if (row >= 0) {
                    __nv_bfloat16 hh, ll;
                    split_bf16(av[r], hh, ll);
                    g_ah[(size_t)row * KV + 33 + tt] = hh;
                    g_al[(size_t)row * KV + 33 + tt] = ll;
                    g_ah[(size_t)row * KV + 128 + tt] = ch;   // folded cproj A-ext
                    g_al[(size_t)row * KV + 128 + tt] = clo;
                }
            }
        }
        // s[row] = q . p0[row] + beta ; warp w handles row w
        {
            int row = srows[warp];
            if (row >= 0) {
                float v = sq[lane] * sp[lane][warp]
                        + sq[lane + 32] * sp[lane + 32][warp]
                        + sq[lane + 64] * sp[lane + 64][warp];
                #pragma unroll
                for (int off = 16; off > 0; off >>= 1)
                    v += __shfl_down_sync(0xffffffffu, v, off);
                if (lane == 0) g_s[row] = v + sbeta;
            }
        }
    }
}

// ---------------------------------------------------------------------------
// wT + uu fused (slot 5): B ext rows — k<128: usr_w[u][k]; 128<=k<223:
// ubias_w[u][33+k-128]; k==223: 0. Blocks y==0 also compute uu.
// ---------------------------------------------------------------------------
__global__ __launch_bounds__(256) void wTuu_kernel(
    const float* __restrict__ usr_w, const float* __restrict__ ubias_w)
{
    __shared__ __align__(16) float tile[32][33];
    const int t = threadIdx.x;
    const int tx = t & 31, ty = t >> 5;
    const int u0 = blockIdx.x * 32;
    const int k0 = blockIdx.y * 32;

    #pragma unroll
    for (int r = 0; r < 4; r++) {
        int u = u0 + ty + r * 8;
        int k = k0 + tx;
        float v = 0.f;
        if (u < NUSER) {
            if (k < 128)      v = usr_w[(size_t)u * 128 + k];
            else if (k < 223) v = ubias_w[(size_t)u * 128 + 33 + (k - 128)];
        }
        tile[ty + r * 8][tx] = v;
    }
    __syncthreads();
    #pragma unroll
    for (int r = 0; r < 4; r++) {
        int k = k0 + ty + r * 8;
        float v = tile[tx][ty + r * 8];
        __nv_bfloat16 h, l;
        split_bf16(v, h, l);
        g_uh[(size_t)k * NU_PAD + u0 + tx] = h;
        g_ul[(size_t)k * NU_PAD + u0 + tx] = l;
    }

    if (blockIdx.y == 0) {
        int u = u0 + (t >> 3);
        if (u < NUSER) {
            const float* a = usr_w + (size_t)u * 128 + (t & 7) * 16;
            const float* b = ubias_w + (size_t)u * 128 + (t & 7) * 16;
            float acc = 0.f;
            #pragma unroll
            for (int k = 0; k < 16; k++) acc += a[k] * b[k];
            #pragma unroll
            for (int off = 4; off > 0; off >>= 1)
                acc += __shfl_down_sync(0xffffffffu, acc, off);
            if ((t & 7) == 0) g_uu[u] = acc;
        }
    }
}

// ---------------------------------------------------------------------------
// Main GEMM (slot 6): bf16 split 3-pass over virtual K=224 (7 chunks of 32),
// 3-stage cp.async ring. out = A~.B~ + s[b] + uu[u].
// ---------------------------------------------------------------------------
#define KC 32
#define NKC 7                       // 224 / 32
#define NCHUNK 21                   // 3 passes x 7
#define ASTRIDE 40
#define BSTRIDE 136
__global__ __launch_bounds__(256) void gemm_mma_kernel(float* __restrict__ out)
{
    __shared__ __align__(16) __nv_bfloat16 Asm[3][128][ASTRIDE];
    __shared__ __align__(16) __nv_bfloat16 Bsm[3][KC][BSTRIDE];
    __shared__ float ss[128];
    __shared__ float su[128];

    const int t = threadIdx.x;
    const int bm = blockIdx.x * 128;
    const int bn = blockIdx.y * 128;

    if (t < 128) {
        ss[t] = g_s[bm + t];
        int n = bn + t;
        su[t] = (n < NUSER) ? g_uu[n] : 0.f;
    }

    const unsigned aBase = (unsigned)__cvta_generic_to_shared(&Asm[0][0][0]);
    const unsigned bBase = (unsigned)__cvta_generic_to_shared(&Bsm[0][0][0]);
    const unsigned aStageB = 128 * ASTRIDE * 2;
    const unsigned bStageB = KC * BSTRIDE * 2;

    const __nv_bfloat16* Alist[3] = {g_ah, g_ah, g_al};
    const __nv_bfloat16* Blist[3] = {g_uh, g_ul, g_uh};

    auto issue = [&](int c, int stage) {
        const int p = c / NKC;
        const int kc = (c - p * NKC) * KC;
        const __nv_bfloat16* As = Alist[p];
        const __nv_bfloat16* Bs = Blist[p];
        #pragma unroll
        for (int i = 0; i < 2; i++) {
            int idx = t * 2 + i;
            int ar = idx >> 2, aseg = (idx & 3) * 8;
            cpasync16(aBase + stage * aStageB + (ar * ASTRIDE + aseg) * 2,
                      As + (size_t)(bm + ar) * KV + kc + aseg);
            int br = idx >> 4, bseg = (idx & 15) * 8;
            cpasync16(bBase + stage * bStageB + (br * BSTRIDE + bseg) * 2,
                      Bs + (size_t)(kc + br) * NU_PAD + bn + bseg);
        }
        cpasync_commit();
    };

    const int warp = t >> 5;
    const int lane = t & 31;
    const int m_base = (warp & 1) * 64;
    const int n_base = (warp >> 1) * 32;

    float acc[4][4][4];
    #pragma unroll
    for (int i = 0; i < 4; i++)
        #pragma unroll
        for (int j = 0; j < 4; j++)
            #pragma unroll
            for (int r = 0; r < 4; r++) acc[i][j][r] = 0.f;

    issue(0, 0);
    issue(1, 1);

    int st = 0;
    #pragma unroll 1
    for (int c = 0; c < NCHUNK; c++) {
        if (c >= NCHUNK - 2) cpasync_wait0(); else cpasync_wait1();
        __syncthreads();

        #pragma unroll
        for (int ks = 0; ks < 2; ks++) {
            unsigned af[4][4];
            #pragma unroll
            for (int mt = 0; mt < 4; mt++) {
                unsigned addr = aBase + st * aStageB +
                    ((m_base + mt * 16 + (lane & 15)) * ASTRIDE + ks * 16 + (lane >> 4) * 8) * 2;
                ldsm_x4(af[mt], addr);
            }
            unsigned bf[2][4];
            #pragma unroll
            for (int np = 0; np < 2; np++) {
                unsigned addr = bBase + st * bStageB +
                    ((ks * 16 + (lane & 15)) * BSTRIDE + n_base + np * 16 + (lane >> 4) * 8) * 2;
                ldsm_x4_t(bf[np], addr);
            }
            #pragma unroll
            for (int mt = 0; mt < 4; mt++)
                #pragma unroll
                for (int nt = 0; nt < 4; nt++)
                    mma16816(acc[mt][nt], af[mt], &bf[nt >> 1][(nt & 1) * 2]);
        }

        if (c + 2 < NCHUNK) {
            int nst = st + 2; if (nst >= 3) nst -= 3;
            issue(c + 2, nst);
        }
        st = (st + 1 == 3) ? 0 : st + 1;
    }

    // epilogue: + s[b] + uu[u]
    const int rl = lane >> 2;
    const int cl = (lane & 3) * 2;
    #pragma unroll
    for (int mt = 0; mt < 4; mt++) {
        #pragma unroll
        for (int half = 0; half < 2; half++) {
            const int ml = m_base + mt * 16 + rl + half * 8;
            const int m = bm + ml;
            const float sb = ss[ml];
            #pragma unroll
            for (int nt = 0; nt < 4; nt++) {
                const int nl = n_base + nt * 8 + cl;
                const int n = bn + nl;
                if (n < NUSER) {
                    float2 o;
                    o.x = acc[mt][nt][half * 2 + 0] + sb + su[nl];
                    o.y = acc[mt][nt][half * 2 + 1] + sb + su[nl + 1];
                    *reinterpret_cast<float2*>(&out[(size_t)m * NUSER + n]) = o;
                }
            }
        }
    }
}

// ---------------------------------------------------------------------------
extern "C" void kernel_launch(void* const* d_in, const int* in_sizes, int n_in,
                              void* d_out, int out_size)
{
    int off = (n_in >= 5 && in_sizes[4] == 1) ? 0 : -1;

    const float* feat      = (const float*)d_in[0];
    const int*   fcat      = (const int*)  d_in[1];
    const float* usr_w     = (const float*)d_in[5 + off];
    const float* cate_w    = (const float*)d_in[6 + off];
    const float* cmat_w    = (const float*)d_in[7 + off];
    const float* cbias_w   = (const float*)d_in[8 + off];
    const float* ubias_w   = (const float*)d_in[9 + off];
    const float* cbiasb_w  = (const float*)d_in[10 + off];
    const float* fc0_w     = (const float*)d_in[11 + off];
    const float* fc0_b     = (const float*)d_in[12 + off];
    const float* cvismat_w = (const float*)d_in[13 + off];
    const float* cvisbias_w= (const float*)d_in[14 + off];
    float* out = (float*)d_out;

    p0hist_kernel<<<160, 256>>>(feat, fc0_w, fc0_b, fcat,
                                cate_w, cmat_w, cbias_w);                  // 1
    scan_kernel<<<1, 256>>>();                                             // 2
    scatter_kernel<<<NB / 256, 256>>>(fcat);                               // 3
    itmq_kernel<<<NCATE, 256>>>(cvismat_w, cvisbias_w, cbiasb_w);          // 4 (profiled)
    wTuu_kernel<<<dim3(32, 7), 256>>>(usr_w, ubias_w);                     // 5
    gemm_mma_kernel<<<dim3(NB / 128, NU_PAD / 128), 256>>>(out);           // 6
}

// round 17
// speedup vs baseline: 1.0776x; 1.0776x over previous
#include <cuda_runtime.h>
#include <cuda_bf16.h>
#include <cstdint>

#define NB    8192
#define NFEAT 128
#define NUSER 1000
#define NU_PAD 1024
#define NCATE 1400
#define NP    95
#define KV    224     // virtual K: 128 pitm + 95 cbiasb + 1 pad

// Scratch (device globals; zero-initialized at module load)
__device__ __align__(256) __nv_bfloat16 g_ah[NB * KV];        // A hi, row-major [b][k]
__device__ __align__(256) __nv_bfloat16 g_al[NB * KV];        // A lo
__device__ __align__(256) __nv_bfloat16 g_uh[KV * NU_PAD];    // B hi, K-major [k][u]
__device__ __align__(256) __nv_bfloat16 g_ul[KV * NU_PAD];    // B lo
__device__ float g_p0[NB * 96];
__device__ float g_s[NB];
__device__ float g_uu[NUSER];
__device__ int   g_cnt[NCATE];   // zero at load; itmq resets after use
__device__ int   g_off[NCATE];
__device__ int   g_cur[NCATE];
__device__ int   g_rows[NB];

// ---------------------------------------------------------------------------
// PTX helpers
// ---------------------------------------------------------------------------
__device__ __forceinline__ void cpasync16(unsigned int dst_smem, const void* src) {
    asm volatile("cp.async.cg.shared.global [%0], [%1], 16;"
                 :: "r"(dst_smem), "l"(src));
}
__device__ __forceinline__ void cpasync4(unsigned int dst_smem, const void* src) {
    asm volatile("cp.async.ca.shared.global [%0], [%1], 4;"
                 :: "r"(dst_smem), "l"(src));
}
__device__ __forceinline__ void cpasync_commit() {
    asm volatile("cp.async.commit_group;" ::: "memory");
}
__device__ __forceinline__ void cpasync_wait1() {
    asm volatile("cp.async.wait_group 1;" ::: "memory");
}
__device__ __forceinline__ void cpasync_wait0() {
    asm volatile("cp.async.wait_group 0;" ::: "memory");
}
__device__ __forceinline__ void ldsm_x4(unsigned* r, unsigned addr) {
    asm volatile("ldmatrix.sync.aligned.m8n8.x4.shared.b16 {%0,%1,%2,%3}, [%4];"
                 : "=r"(r[0]), "=r"(r[1]), "=r"(r[2]), "=r"(r[3]) : "r"(addr));
}
__device__ __forceinline__ void ldsm_x4_t(unsigned* r, unsigned addr) {
    asm volatile("ldmatrix.sync.aligned.m8n8.x4.trans.shared.b16 {%0,%1,%2,%3}, [%4];"
                 : "=r"(r[0]), "=r"(r[1]), "=r"(r[2]), "=r"(r[3]) : "r"(addr));
}
__device__ __forceinline__ void mma16816(float* c, const unsigned* a, const unsigned* b) {
    asm volatile(
        "mma.sync.aligned.m16n8k16.row.col.f32.bf16.bf16.f32 "
        "{%0,%1,%2,%3}, {%4,%5,%6,%7}, {%8,%9}, {%0,%1,%2,%3};"
        : "+f"(c[0]), "+f"(c[1]), "+f"(c[2]), "+f"(c[3])
        : "r"(a[0]), "r"(a[1]), "r"(a[2]), "r"(a[3]), "r"(b[0]), "r"(b[1]));
}
__device__ __forceinline__ void split_bf16(float x, __nv_bfloat16& h, __nv_bfloat16& l) {
    h = __float2bfloat16(x);
    l = __float2bfloat16(x - __bfloat162float(h));
}

// ---------------------------------------------------------------------------
// p0 + hist (slot 1): p0 GEMM, 64 rows per block (vectorized inner loop);
// threads t<64 also histogram their row's c2.
// ---------------------------------------------------------------------------
__global__ __launch_bounds__(256, 2) void p0hist_kernel(
    const float* __restrict__ feat, const float* __restrict__ fc0_w,
    const float* __restrict__ fc0_b, const int* __restrict__ fcat)
{
    __shared__ __align__(16) float sw[128 * 100];
    __shared__ __align__(16) float sf[128 * 65];

    const int t = threadIdx.x;
    const int bm = blockIdx.x * 64;

    if (t < 64) atomicAdd(&g_cnt[fcat[3 * (bm + t) + 2]], 1);

    for (int L = t; L < NP * 128; L += 256) {
        int n = L >> 7, k = L & 127;
        sw[k * 100 + n] = fc0_w[L];
    }
    for (int L = t; L < 64 * 128; L += 256) {
        int m = L >> 7, k = L & 127;
        sf[k * 65 + m] = feat[(bm + m) * 128 + k];
    }
    __syncthreads();

    const int m  = t & 63;
    const int n0 = (t >> 6) * 24;   // 0,24,48,72 — 96B groups, 16B-aligned

    float acc[24];
    #pragma unroll
    for (int j = 0; j < 24; j++)
        acc[j] = (n0 + j < NP) ? fc0_b[n0 + j] : 0.f;

    #pragma unroll 4
    for (int k = 0; k < 128; k++) {
        float a = sf[k * 65 + m];
        const float4* wr4 = reinterpret_cast<const float4*>(&sw[k * 100 + n0]);
        #pragma unroll
        for (int q = 0; q < 6; q++) {
            float4 w = wr4[q];
            acc[q * 4 + 0] += a * w.x;
            acc[q * 4 + 1] += a * w.y;
            acc[q * 4 + 2] += a * w.z;
            acc[q * 4 + 3] += a * w.w;
        }
    }

    float* dst = &g_p0[(size_t)(bm + m) * 96 + n0];
    #pragma unroll
    for (int j = 0; j < 24; j++)
        if (n0 + j < 96) dst[j] = (n0 + j < NP) ? acc[j] : 0.f;
}

// ---------------------------------------------------------------------------
// scan (slot 2)
// ---------------------------------------------------------------------------
__global__ __launch_bounds__(256) void scan_kernel() {
    __shared__ int wsum[8];
    __shared__ int wexcl[8];
    const int t = threadIdx.x;
    const int lane = t & 31, warp = t >> 5;
    const int base = t * 6;
    int local[6];
    int s = 0;
    #pragma unroll
    for (int j = 0; j < 6; j++) {
        int idx = base + j;
        int v = (idx < NCATE) ? g_cnt[idx] : 0;
        local[j] = s;
        s += v;
    }
    int x = s;
    #pragma unroll
    for (int off = 1; off < 32; off <<= 1) {
        int y = __shfl_up_sync(0xffffffffu, x, off);
        if (lane >= off) x += y;
    }
    if (lane == 31) wsum[warp] = x;
    __syncthreads();
    if (warp == 0 && lane < 8) {
        int w = wsum[lane];
        int xx = w;
        #pragma unroll
        for (int off = 1; off < 8; off <<= 1) {
            int y = __shfl_up_sync(0xffu, xx, off);
            if (lane >= off) xx += y;
        }
        wexcl[lane] = xx - w;
    }
    __syncthreads();
    const int excl = (x - s) + wexcl[warp];
    #pragma unroll
    for (int j = 0; j < 6; j++) {
        int idx = base + j;
        if (idx < NCATE) {
            int o = excl + local[j];
            g_off[idx] = o;
            g_cur[idx] = o;
        }
    }
}

// ---------------------------------------------------------------------------
// scatter + cat chain fused (slot 3)
// ---------------------------------------------------------------------------
__global__ __launch_bounds__(256) void scatcat_kernel(
    const int* __restrict__ fcat,
    const float* __restrict__ cate_w, const float* __restrict__ cmat_w,
    const float* __restrict__ cbias_w)
{
    int b = blockIdx.x * 256 + threadIdx.x;
    if (b >= NB) return;
    const int c0 = fcat[3 * b + 0];
    const int c1 = fcat[3 * b + 1];
    const int c2 = fcat[3 * b + 2];

    int pos = atomicAdd(&g_cur[c2], 1);
    g_rows[pos] = b;

    float cat1[11], cat2[11], cat3[11];
    #pragma unroll
    for (int j = 0; j < 11; j++) cat1[j] = cate_w[c0 * 11 + j];
    const float* m1 = cmat_w + c1 * 121;
    #pragma unroll
    for (int i = 0; i < 11; i++) {
        float a = cbias_w[c1 * 11 + i];
        #pragma unroll
        for (int j = 0; j < 11; j++) a += m1[i * 11 + j] * cat1[j];
        cat2[i] = a;
    }
    const float* m2 = cmat_w + c2 * 121;
    #pragma unroll
    for (int i = 0; i < 11; i++) {
        float a = cbias_w[c2 * 11 + i];
        #pragma unroll
        for (int j = 0; j < 11; j++) a += m2[i * 11 + j] * cat2[j];
        cat3[i] = a;
    }
    __nv_bfloat16* ah = &g_ah[(size_t)b * KV];
    __nv_bfloat16* al = &g_al[(size_t)b * KV];
    #pragma unroll
    for (int j = 0; j < 11; j++) {
        __nv_bfloat16 h, l;
        split_bf16(cat1[j], h, l); ah[j] = h;      al[j] = l;
        split_bf16(cat2[j], h, l); ah[11 + j] = h; al[11 + j] = l;
        split_bf16(cat3[j], h, l); ah[22 + j] = h; al[22 + j] = l;
    }
    ah[223] = __float2bfloat16(0.f);
    al[223] = __float2bfloat16(0.f);
}

// ---------------------------------------------------------------------------
// itmq (slot 4 -- gets profiled): cp.async-staged M (row-major, stride 95 —
// conflict-free both directions since 95 ≡ -1 mod 32). A cols 33..127 (itmq),
// 128..222 (cbiasb split); s[b] = q.p0 + beta. Race-free count reset.
// ---------------------------------------------------------------------------
__global__ __launch_bounds__(256) void itmq_kernel(
    const float* __restrict__ cvismat_w, const float* __restrict__ cvisbias_w,
    const float* __restrict__ cbiasb_w)
{
    const int c = blockIdx.x;

    __shared__ int sn;
    if (threadIdx.x == 0) { sn = g_cnt[c]; g_cnt[c] = 0; }
    __syncthreads();
    const int n = sn;
    if (n == 0) return;

    __shared__ __align__(16) float sM[NP * NP];    // row-major M, 36.1 KB
    __shared__ __align__(16) float sp[96][8];      // [j][row] (float4-accessed)
    __shared__ __align__(16) float sq[96];
    __shared__ __align__(16) float svb[96];
    __shared__ __align__(16) float scb[96];
    __shared__ __nv_bfloat16 scbh[96];
    __shared__ __nv_bfloat16 scbl[96];
    __shared__ float sbeta;
    __shared__ int   srows[8];

    const int t = threadIdx.x;
    const int warp = t >> 5, lane = t & 31;

    // async stage M: 4-byte cp.async, fully coalesced, no latency exposure
    {
        const float* Msrc = cvismat_w + (size_t)c * (NP * NP);
        unsigned sMb = (unsigned)__cvta_generic_to_shared(sM);
        #pragma unroll 9
        for (int idx = t; idx < NP * NP; idx += 256)
            cpasync4(sMb + idx * 4u, Msrc + idx);
        cpasync_commit();
    }
    // overlapped: cb/vb loads, first-batch row ids
    if (t < NP) {
        float cbv = cbiasb_w[c * NP + t];
        scb[t] = cbv;
        svb[t] = cvisbias_w[c * NP + t];
        __nv_bfloat16 h, l;
        split_bf16(cbv, h, l);
        scbh[t] = h; scbl[t] = l;
    }
    if (t == NP) { scb[NP] = 0.f; svb[NP] = 0.f; }
    const int start = g_off[c];
    if (t < 8) srows[t] = (t < n) ? g_rows[start + t] : -1;
    __syncthreads();   // srows/scb/svb visible

    // overlapped: gather p0 batch 0 while M copies fly
    for (int L = t; L < 1024; L += 256) {
        int r = L >> 7, j = L & 127;
        if (j < 96) {
            int row = srows[r];
            sp[j][r] = (row >= 0) ? g_p0[(size_t)row * 96 + j] : 0.f;
        }
    }
    cpasync_wait0();
    __syncthreads();   // M + sp visible

    // q[j] = sum_i cb[i] * M[i][j], 4 split accumulators
    if (t < NP) {
        float q0 = 0.f, q1 = 0.f, q2 = 0.f, q3 = 0.f;
        #pragma unroll 4
        for (int i = 0; i < 92; i += 4) {
            q0 += scb[i + 0] * sM[(i + 0) * NP + t];
            q1 += scb[i + 1] * sM[(i + 1) * NP + t];
            q2 += scb[i + 2] * sM[(i + 2) * NP + t];
            q3 += scb[i + 3] * sM[(i + 3) * NP + t];
        }
        q0 += scb[92] * sM[92 * NP + t];
        q1 += scb[93] * sM[93 * NP + t];
        q2 += scb[94] * sM[94 * NP + t];
        sq[t] = (q0 + q1) + (q2 + q3);
    }
    if (t == NP) sq[NP] = 0.f;
    if (warp == 0) {
        float v = scb[lane] * svb[lane] + scb[lane + 32] * svb[lane + 32]
                + scb[lane + 64] * svb[lane + 64];
        #pragma unroll
        for (int off = 16; off > 0; off >>= 1)
            v += __shfl_down_sync(0xffffffffu, v, off);
        if (lane == 0) sbeta = v;
    }
    __syncthreads();   // sq, sbeta visible

    const int h = t >> 7, tt = t & 127;

    for (int i0 = 0; i0 < n; i0 += 8) {
        if (i0 > 0) {
            __syncthreads();   // previous compute done reading sp
            if (t < 8) srows[t] = (i0 + t < n) ? g_rows[start + i0 + t] : -1;
            __syncthreads();
            for (int L = t; L < 1024; L += 256) {
                int r = L >> 7, j = L & 127;
                if (j < 96) {
                    int row = srows[r];
                    sp[j][r] = (row >= 0) ? g_p0[(size_t)row * 96 + j] : 0.f;
                }
            }
            __syncthreads();
        }

        if (tt < NP) {
            float a0 = svb[tt], a1 = a0, a2 = a0, a3 = a0;
            const float* mr = &sM[tt * NP];
            #pragma unroll 5
            for (int j = 0; j < NP; j++) {
                float m = mr[j];
                float4 pv = *reinterpret_cast<const float4*>(&sp[j][h * 4]);
                a0 += m * pv.x; a1 += m * pv.y; a2 += m * pv.z; a3 += m * pv.w;
            }
            float av[4] = {a0, a1, a2, a3};
            __nv_bfloat16 ch = scbh[tt], clo = scbl[tt];
            #pragma unroll
            for (int r = 0; r < 4; r++) {
                int row = srows[h * 4 + r];
                if (row >= 0) {
                    __nv_bfloat16 hh, ll;
                    split_bf16(av[r], hh, ll);
                    g_ah[(size_t)row * KV + 33 + tt] = hh;
                    g_al[(size_t)row * KV + 33 + tt] = ll;
                    g_ah[(size_t)row * KV + 128 + tt] = ch;   // folded cproj A-ext
                    g_al[(size_t)row * KV + 128 + tt] = clo;
                }
            }
        }
        // s[row] = q . p0[row] + beta ; warp w handles row w
        {
            int row = srows[warp];
            if (row >= 0) {
                float v = sq[lane] * sp[lane][warp]
                        + sq[lane + 32] * sp[lane + 32][warp]
                        + sq[lane + 64] * sp[lane + 64][warp];
                #pragma unroll
                for (int off = 16; off > 0; off >>= 1)
                    v += __shfl_down_sync(0xffffffffu, v, off);
                if (lane == 0) g_s[row] = v + sbeta;
            }
        }
    }
}

// ---------------------------------------------------------------------------
// wT + uu fused (slot 5): B ext rows — k<128: usr_w[u][k]; 128<=k<223:
// ubias_w[u][33+k-128]; k==223: 0. Blocks y==0 also compute uu.
// ---------------------------------------------------------------------------
__global__ __launch_bounds__(256) void wTuu_kernel(
    const float* __restrict__ usr_w, const float* __restrict__ ubias_w)
{
    __shared__ __align__(16) float tile[32][33];
    const int t = threadIdx.x;
    const int tx = t & 31, ty = t >> 5;
    const int u0 = blockIdx.x * 32;
    const int k0 = blockIdx.y * 32;

    #pragma unroll
    for (int r = 0; r < 4; r++) {
        int u = u0 + ty + r * 8;
        int k = k0 + tx;
        float v = 0.f;
        if (u < NUSER) {
            if (k < 128)      v = usr_w[(size_t)u * 128 + k];
            else if (k < 223) v = ubias_w[(size_t)u * 128 + 33 + (k - 128)];
        }
        tile[ty + r * 8][tx] = v;
    }
    __syncthreads();
    #pragma unroll
    for (int r = 0; r < 4; r++) {
        int k = k0 + ty + r * 8;
        float v = tile[tx][ty + r * 8];
        __nv_bfloat16 h, l;
        split_bf16(v, h, l);
        g_uh[(size_t)k * NU_PAD + u0 + tx] = h;
        g_ul[(size_t)k * NU_PAD + u0 + tx] = l;
    }

    if (blockIdx.y == 0) {
        int u = u0 + (t >> 3);
        if (u < NUSER) {
            const float* a = usr_w + (size_t)u * 128 + (t & 7) * 16;
            const float* b = ubias_w + (size_t)u * 128 + (t & 7) * 16;
            float acc = 0.f;
            #pragma unroll
            for (int k = 0; k < 16; k++) acc += a[k] * b[k];
            #pragma unroll
            for (int off = 4; off > 0; off >>= 1)
                acc += __shfl_down_sync(0xffffffffu, acc, off);
            if ((t & 7) == 0) g_uu[u] = acc;
        }
    }
}

// ---------------------------------------------------------------------------
// Main GEMM (slot 6): bf16 split 3-pass over virtual K=224 (7 chunks of 32),
// 3-stage cp.async ring. out = A~.B~ + s[b] + uu[u].
// ---------------------------------------------------------------------------
#define KC 32
#define NKC 7                       // 224 / 32
#define NCHUNK 21                   // 3 passes x 7
#define ASTRIDE 40
#define BSTRIDE 136
__global__ __launch_bounds__(256) void gemm_mma_kernel(float* __restrict__ out)
{
    __shared__ __align__(16) __nv_bfloat16 Asm[3][128][ASTRIDE];
    __shared__ __align__(16) __nv_bfloat16 Bsm[3][KC][BSTRIDE];
    __shared__ float ss[128];
    __shared__ float su[128];

    const int t = threadIdx.x;
    const int bm = blockIdx.x * 128;
    const int bn = blockIdx.y * 128;

    if (t < 128) {
        ss[t] = g_s[bm + t];
        int n = bn + t;
        su[t] = (n < NUSER) ? g_uu[n] : 0.f;
    }

    const unsigned aBase = (unsigned)__cvta_generic_to_shared(&Asm[0][0][0]);
    const unsigned bBase = (unsigned)__cvta_generic_to_shared(&Bsm[0][0][0]);
    const unsigned aStageB = 128 * ASTRIDE * 2;
    const unsigned bStageB = KC * BSTRIDE * 2;

    const __nv_bfloat16* Alist[3] = {g_ah, g_ah, g_al};
    const __nv_bfloat16* Blist[3] = {g_uh, g_ul, g_uh};

    auto issue = [&](int c, int stage) {
        const int p = c / NKC;
        const int kc = (c - p * NKC) * KC;
        const __nv_bfloat16* As = Alist[p];
        const __nv_bfloat16* Bs = Blist[p];
        #pragma unroll
        for (int i = 0; i < 2; i++) {
            int idx = t * 2 + i;
            int ar = idx >> 2, aseg = (idx & 3) * 8;
            cpasync16(aBase + stage * aStageB + (ar * ASTRIDE + aseg) * 2,
                      As + (size_t)(bm + ar) * KV + kc + aseg);
            int br = idx >> 4, bseg = (idx & 15) * 8;
            cpasync16(bBase + stage * bStageB + (br * BSTRIDE + bseg) * 2,
                      Bs + (size_t)(kc + br) * NU_PAD + bn + bseg);
        }
        cpasync_commit();
    };

    const int warp = t >> 5;
    const int lane = t & 31;
    const int m_base = (warp & 1) * 64;
    const int n_base = (warp >> 1) * 32;

    float acc[4][4][4];
    #pragma unroll
    for (int i = 0; i < 4; i++)
        #pragma unroll
        for (int j = 0; j < 4; j++)
            #pragma unroll
            for (int r = 0; r < 4; r++) acc[i][j][r] = 0.f;

    issue(0, 0);
    issue(1, 1);

    int st = 0;
    #pragma unroll 1
    for (int c = 0; c < NCHUNK; c++) {
        if (c >= NCHUNK - 2) cpasync_wait0(); else cpasync_wait1();
        __syncthreads();

        #pragma unroll
        for (int ks = 0; ks < 2; ks++) {
            unsigned af[4][4];
            #pragma unroll
            for (int mt = 0; mt < 4; mt++) {
                unsigned addr = aBase + st * aStageB +
                    ((m_base + mt * 16 + (lane & 15)) * ASTRIDE + ks * 16 + (lane >> 4) * 8) * 2;
                ldsm_x4(af[mt], addr);
            }
            unsigned bf[2][4];
            #pragma unroll
            for (int np = 0; np < 2; np++) {
                unsigned addr = bBase + st * bStageB +
                    ((ks * 16 + (lane & 15)) * BSTRIDE + n_base + np * 16 + (lane >> 4) * 8) * 2;
                ldsm_x4_t(bf[np], addr);
            }
            #pragma unroll
            for (int mt = 0; mt < 4; mt++)
                #pragma unroll
                for (int nt = 0; nt < 4; nt++)
                    mma16816(acc[mt][nt], af[mt], &bf[nt >> 1][(nt & 1) * 2]);
        }

        if (c + 2 < NCHUNK) {
            int nst = st + 2; if (nst >= 3) nst -= 3;
            issue(c + 2, nst);
        }
        st = (st + 1 == 3) ? 0 : st + 1;
    }

    // epilogue: + s[b] + uu[u]
    const int rl = lane >> 2;
    const int cl = (lane & 3) * 2;
    #pragma unroll
    for (int mt = 0; mt < 4; mt++) {
        #pragma unroll
        for (int half = 0; half < 2; half++) {
            const int ml = m_base + mt * 16 + rl + half * 8;
            const int m = bm + ml;
            const float sb = ss[ml];
            #pragma unroll
            for (int nt = 0; nt < 4; nt++) {
                const int nl = n_base + nt * 8 + cl;
                const int n = bn + nl;
                if (n < NUSER) {
                    float2 o;
                    o.x = acc[mt][nt][half * 2 + 0] + sb + su[nl];
                    o.y = acc[mt][nt][half * 2 + 1] + sb + su[nl + 1];
                    *reinterpret_cast<float2*>(&out[(size_t)m * NUSER + n]) = o;
                }
            }
        }
    }
}

// ---------------------------------------------------------------------------
extern "C" void kernel_launch(void* const* d_in, const int* in_sizes, int n_in,
                              void* d_out, int out_size)
{
    int off = (n_in >= 5 && in_sizes[4] == 1) ? 0 : -1;

    const float* feat      = (const float*)d_in[0];
    const int*   fcat      = (const int*)  d_in[1];
    const float* usr_w     = (const float*)d_in[5 + off];
    const float* cate_w    = (const float*)d_in[6 + off];
    const float* cmat_w    = (const float*)d_in[7 + off];
    const float* cbias_w   = (const float*)d_in[8 + off];
    const float* ubias_w   = (const float*)d_in[9 + off];
    const float* cbiasb_w  = (const float*)d_in[10 + off];
    const float* fc0_w     = (const float*)d_in[11 + off];
    const float* fc0_b     = (const float*)d_in[12 + off];
    const float* cvismat_w = (const float*)d_in[13 + off];
    const float* cvisbias_w= (const float*)d_in[14 + off];
    float* out = (float*)d_out;

    p0hist_kernel<<<NB / 64, 256>>>(feat, fc0_w, fc0_b, fcat);             // 1
    scan_kernel<<<1, 256>>>();                                             // 2
    scatcat_kernel<<<NB / 256, 256>>>(fcat, cate_w, cmat_w, cbias_w);      // 3
    itmq_kernel<<<NCATE, 256>>>(cvismat_w, cvisbias_w, cbiasb_w);          // 4 (profiled)
    wTuu_kernel<<<dim3(32, 7), 256>>>(usr_w, ubias_w);                     // 5
    gemm_mma_kernel<<<dim3(NB / 128, NU_PAD / 128), 256>>>(out);           // 6
}